// round 4
// baseline (speedup 1.0000x reference)
#include <cuda_runtime.h>

#define NMAX 50000
#define EMAX 1600000
#define DD 128

// ---- scratch (static device globals; no allocation allowed) ----
__device__ float g_sup[(size_t)NMAX * DD];   // support = X @ W
__device__ float g_h[(size_t)NMAX * DD];     // hidden after layer 1
__device__ int   g_rowptr[NMAX + 1];
__device__ int   g_deg[NMAX];
__device__ int   g_fill[NMAX];
__device__ int   g_csrs[EMAX];
__device__ float g_csrw[EMAX];
__device__ int   g_part[256];

// ================= CSR build =================

__global__ void k_zero_deg(int n) {
    int i = blockIdx.x * blockDim.x + threadIdx.x;
    if (i < n) g_deg[i] = 0;
}

__global__ void k_hist(const int* __restrict__ dst, int e) {
    int i = blockIdx.x * blockDim.x + threadIdx.x;
    if (i < e) atomicAdd(&g_deg[dst[i]], 1);
}

__global__ void k_scan_partial(int n) {
    __shared__ int sm[256];
    int t = threadIdx.x;
    int i = blockIdx.x * 256 + t;
    int v = (i < n) ? g_deg[i] : 0;
    sm[t] = v;
    __syncthreads();
    for (int off = 128; off > 0; off >>= 1) {
        if (t < off) sm[t] += sm[t + off];
        __syncthreads();
    }
    if (t == 0) g_part[blockIdx.x] = sm[0];
}

__global__ void k_scan_top(int nch) {
    __shared__ int sm[256];
    int t = threadIdx.x;
    int v = (t < nch) ? g_part[t] : 0;
    int x = v;
    sm[t] = x;
    __syncthreads();
    for (int off = 1; off < 256; off <<= 1) {
        int y = (t >= off) ? sm[t - off] : 0;
        __syncthreads();
        x += y;
        sm[t] = x;
        __syncthreads();
    }
    if (t < nch) g_part[t] = x - v;   // exclusive prefix of chunk sums
}

__global__ void k_scan_final(int n, int e) {
    __shared__ int sm[256];
    int t = threadIdx.x;
    int i = blockIdx.x * 256 + t;
    int v = (i < n) ? g_deg[i] : 0;
    int x = v;
    sm[t] = x;
    __syncthreads();
    for (int off = 1; off < 256; off <<= 1) {
        int y = (t >= off) ? sm[t - off] : 0;
        __syncthreads();
        x += y;
        sm[t] = x;
        __syncthreads();
    }
    int base = g_part[blockIdx.x];
    if (i < n) {
        int ex = base + x - v;
        g_rowptr[i] = ex;
        g_fill[i] = ex;
    }
    if (i == 0) g_rowptr[n] = e;
}

__global__ void k_fill(const int* __restrict__ src, const int* __restrict__ dst,
                       const float* __restrict__ w, int e) {
    int i = blockIdx.x * blockDim.x + threadIdx.x;
    if (i < e) {
        int d = dst[i];
        int p = atomicAdd(&g_fill[d], 1);
        g_csrs[p] = src[i];
        g_csrw[p] = w[i];
    }
}

// ================= GEMM: C[n x 128] = X[n x 128] @ W[128 x 128] =================
// 256 threads, block tile 128x128, BK=32, 8x8 per-thread register tile.

__global__ __launch_bounds__(256, 2) void k_gemm(const float* __restrict__ X,
                                                 const float* __restrict__ W,
                                                 float* __restrict__ C, int n) {
    __shared__ float Ws[32][128];   // [k][col]
    __shared__ float Xs[32][132];   // [k][row], padded (132*4 = 528 B, 16B-aligned rows)

    int t = threadIdx.x;
    int tx = t & 15;        // col group
    int ty = t >> 4;        // row group
    int rowBase = blockIdx.x * 128;

    float acc[8][8];
#pragma unroll
    for (int i = 0; i < 8; i++)
#pragma unroll
        for (int j = 0; j < 8; j++) acc[i][j] = 0.0f;

    for (int kk = 0; kk < 128; kk += 32) {
        // load W chunk: 32 rows x 128 cols = 1024 float4
#pragma unroll
        for (int i = 0; i < 4; i++) {
            int f = t + 256 * i;
            int wr = f >> 5;         // 0..31
            int wc4 = f & 31;        // float4 index in row
            float4 v = *reinterpret_cast<const float4*>(W + (kk + wr) * 128 + wc4 * 4);
            *reinterpret_cast<float4*>(&Ws[wr][wc4 * 4]) = v;
        }
        // load X chunk transposed: 128 rows x 32 cols = 1024 float4
#pragma unroll
        for (int i = 0; i < 4; i++) {
            int f = t + 256 * i;
            int xr = f >> 3;         // 0..127
            int xc4 = f & 7;         // float4 index within 32-col chunk
            int gr = rowBase + xr;
            float4 v = make_float4(0.f, 0.f, 0.f, 0.f);
            if (gr < n) v = *reinterpret_cast<const float4*>(X + (size_t)gr * 128 + kk + xc4 * 4);
            Xs[xc4 * 4 + 0][xr] = v.x;
            Xs[xc4 * 4 + 1][xr] = v.y;
            Xs[xc4 * 4 + 2][xr] = v.z;
            Xs[xc4 * 4 + 3][xr] = v.w;
        }
        __syncthreads();

#pragma unroll
        for (int k = 0; k < 32; k++) {
            float4 x0 = *reinterpret_cast<const float4*>(&Xs[k][ty * 4]);
            float4 x1 = *reinterpret_cast<const float4*>(&Xs[k][64 + ty * 4]);
            float4 w0 = *reinterpret_cast<const float4*>(&Ws[k][tx * 4]);
            float4 w1 = *reinterpret_cast<const float4*>(&Ws[k][64 + tx * 4]);
            float xv[8] = {x0.x, x0.y, x0.z, x0.w, x1.x, x1.y, x1.z, x1.w};
            float wv[8] = {w0.x, w0.y, w0.z, w0.w, w1.x, w1.y, w1.z, w1.w};
#pragma unroll
            for (int i = 0; i < 8; i++)
#pragma unroll
                for (int j = 0; j < 8; j++) acc[i][j] += xv[i] * wv[j];
        }
        __syncthreads();
    }

    // store
#pragma unroll
    for (int i = 0; i < 8; i++) {
        int rl = (i < 4) ? (ty * 4 + i) : (64 + ty * 4 + (i - 4));
        int gr = rowBase + rl;
        if (gr < n) {
            float4 v0 = make_float4(acc[i][0], acc[i][1], acc[i][2], acc[i][3]);
            float4 v1 = make_float4(acc[i][4], acc[i][5], acc[i][6], acc[i][7]);
            *reinterpret_cast<float4*>(C + (size_t)gr * 128 + tx * 4) = v0;
            *reinterpret_cast<float4*>(C + (size_t)gr * 128 + 64 + tx * 4) = v1;
        }
    }
}

// ================= SpMM (CSR by dst, warp per row, no atomics) =================

__global__ void k_spmm(const float* __restrict__ sup, const float* __restrict__ bias,
                       float* __restrict__ out, int n, int do_relu) {
    int gt = blockIdx.x * blockDim.x + threadIdx.x;
    int row = gt >> 5;
    int lane = gt & 31;
    if (row >= n) return;

    float4 acc = *reinterpret_cast<const float4*>(bias + lane * 4);
    int e0 = g_rowptr[row];
    int e1 = g_rowptr[row + 1];

    for (int e = e0; e < e1; e++) {
        int s = __ldg(&g_csrs[e]);
        float w = __ldg(&g_csrw[e]);
        float4 v = *reinterpret_cast<const float4*>(sup + (size_t)s * 128 + lane * 4);
        acc.x += w * v.x;
        acc.y += w * v.y;
        acc.z += w * v.z;
        acc.w += w * v.w;
    }

    if (do_relu) {
        acc.x = fmaxf(acc.x, 0.f);
        acc.y = fmaxf(acc.y, 0.f);
        acc.z = fmaxf(acc.z, 0.f);
        acc.w = fmaxf(acc.w, 0.f);
    }
    *reinterpret_cast<float4*>(out + (size_t)row * 128 + lane * 4) = acc;
}

// ================= launch =================

extern "C" void kernel_launch(void* const* d_in, const int* in_sizes, int n_in,
                              void* d_out, int out_size) {
    const float* features = (const float*)d_in[0];
    const int*   edge_src = (const int*)d_in[1];
    const int*   edge_dst = (const int*)d_in[2];
    const float* edge_w   = (const float*)d_in[3];
    const float* W1       = (const float*)d_in[4];
    const float* b1       = (const float*)d_in[5];
    const float* W2       = (const float*)d_in[6];
    const float* b2       = (const float*)d_in[7];
    float* out = (float*)d_out;

    int n = in_sizes[0] / DD;   // 50000
    int e = in_sizes[1];        // 1600000

    int nch = (n + 255) / 256;  // scan chunks (<=256 required)

    // ---- CSR build (by dst) ----
    k_zero_deg<<<(n + 255) / 256, 256>>>(n);
    k_hist<<<(e + 255) / 256, 256>>>(edge_dst, e);
    k_scan_partial<<<nch, 256>>>(n);
    k_scan_top<<<1, 256>>>(nch);
    k_scan_final<<<nch, 256>>>(n, e);
    k_fill<<<(e + 255) / 256, 256>>>(edge_src, edge_dst, edge_w, e);

    // pointers to device globals for alternating buffers
    float *sup, *h;
    cudaGetSymbolAddress((void**)&sup, g_sup);
    cudaGetSymbolAddress((void**)&h, g_h);

    int gemm_blocks = (n + 127) / 128;
    int spmm_blocks = (n * 32 + 255) / 256;

    // ---- layer 1 ----
    k_gemm<<<gemm_blocks, 256>>>(features, W1, sup, n);
    k_spmm<<<spmm_blocks, 256>>>(sup, b1, h, n, 1);

    // ---- layer 2 ----
    k_gemm<<<gemm_blocks, 256>>>(h, W2, sup, n);
    k_spmm<<<spmm_blocks, 256>>>(sup, b2, out, n, 0);
}

// round 5
// speedup vs baseline: 1.0628x; 1.0628x over previous
#include <cuda_runtime.h>

#define NMAX 50000
#define EMAX 1600000
#define DD 128

typedef unsigned long long u64;

// ---- scratch (static device globals; no allocation allowed) ----
__device__ float g_sup[(size_t)NMAX * DD];   // support = X @ W
__device__ float g_h[(size_t)NMAX * DD];     // hidden after layer 1
__device__ int   g_rowptr[NMAX + 1];
__device__ int   g_deg[NMAX];
__device__ int   g_fill[NMAX];
__device__ int   g_csrs[EMAX];
__device__ float g_csrw[EMAX];
__device__ int   g_part[256];

// ---- packed f32x2 helpers (FFMA2 path; full fp32 precision) ----
__device__ __forceinline__ u64 pack2f(float a, float b) {
    u64 d;
    asm("mov.b64 %0, {%1, %2};" : "=l"(d)
        : "r"(__float_as_uint(a)), "r"(__float_as_uint(b)));
    return d;
}
__device__ __forceinline__ u64 ffma2(u64 a, u64 b, u64 c) {
    u64 d;
    asm("fma.rn.f32x2 %0, %1, %2, %3;" : "=l"(d) : "l"(a), "l"(b), "l"(c));
    return d;
}
__device__ __forceinline__ void unpack2f(u64 v, float& a, float& b) {
    unsigned int lo, hi;
    asm("mov.b64 {%0, %1}, %2;" : "=r"(lo), "=r"(hi) : "l"(v));
    a = __uint_as_float(lo);
    b = __uint_as_float(hi);
}

// ================= CSR build =================

__global__ void k_hist(const int* __restrict__ dst, int e) {
    int i = blockIdx.x * blockDim.x + threadIdx.x;
    if (i < e) atomicAdd(&g_deg[dst[i]], 1);
}

__global__ void k_scan_partial(int n) {
    __shared__ int sm[256];
    int t = threadIdx.x;
    int i = blockIdx.x * 256 + t;
    int v = (i < n) ? g_deg[i] : 0;
    sm[t] = v;
    __syncthreads();
    for (int off = 128; off > 0; off >>= 1) {
        if (t < off) sm[t] += sm[t + off];
        __syncthreads();
    }
    if (t == 0) g_part[blockIdx.x] = sm[0];
}

__global__ void k_scan_top(int nch) {
    __shared__ int sm[256];
    int t = threadIdx.x;
    int v = (t < nch) ? g_part[t] : 0;
    int x = v;
    sm[t] = x;
    __syncthreads();
    for (int off = 1; off < 256; off <<= 1) {
        int y = (t >= off) ? sm[t - off] : 0;
        __syncthreads();
        x += y;
        sm[t] = x;
        __syncthreads();
    }
    if (t < nch) g_part[t] = x - v;   // exclusive prefix of chunk sums
}

__global__ void k_scan_final(int n, int e) {
    __shared__ int sm[256];
    int t = threadIdx.x;
    int i = blockIdx.x * 256 + t;
    int v = (i < n) ? g_deg[i] : 0;
    int x = v;
    sm[t] = x;
    __syncthreads();
    for (int off = 1; off < 256; off <<= 1) {
        int y = (t >= off) ? sm[t - off] : 0;
        __syncthreads();
        x += y;
        sm[t] = x;
        __syncthreads();
    }
    int base = g_part[blockIdx.x];
    if (i < n) {
        int ex = base + x - v;
        g_rowptr[i] = ex;
        g_fill[i] = ex;
    }
    if (i == 0) g_rowptr[n] = e;
}

__global__ void k_fill(const int* __restrict__ src, const int* __restrict__ dst,
                       const float* __restrict__ w, int e) {
    int i = blockIdx.x * blockDim.x + threadIdx.x;
    if (i < e) {
        int d = dst[i];
        int p = atomicAdd(&g_fill[d], 1);
        g_csrs[p] = src[i];
        g_csrw[p] = w[i];
    }
}

// ================= GEMM: C[n x 128] = X[n x 128] @ W[128 x 128] =================
// 256 threads, block tile 128x128, BK=32, 8x8 per-thread tile, FFMA2 (f32x2) inner loop.

__global__ __launch_bounds__(256, 2) void k_gemm(const float* __restrict__ X,
                                                 const float* __restrict__ W,
                                                 float* __restrict__ C, int n) {
    __shared__ float Ws[32][128];   // [k][col]
    __shared__ float Xs[32][132];   // [k][row], padded

    int t = threadIdx.x;
    int tx = t & 15;        // col group
    int ty = t >> 4;        // row group
    int rowBase = blockIdx.x * 128;

    // acc2[i][j] holds cols pair: j=0 -> (tx*4, tx*4+1), j=1 -> (tx*4+2, +3),
    // j=2 -> (64+tx*4, +1), j=3 -> (64+tx*4+2, +3)
    u64 acc2[8][4];
#pragma unroll
    for (int i = 0; i < 8; i++)
#pragma unroll
        for (int j = 0; j < 4; j++) acc2[i][j] = 0ull;   // bits of (0.0f, 0.0f)

    for (int kk = 0; kk < 128; kk += 32) {
        // load W chunk: 32 rows x 128 cols = 1024 float4
#pragma unroll
        for (int i = 0; i < 4; i++) {
            int f = t + 256 * i;
            int wr = f >> 5;
            int wc4 = f & 31;
            float4 v = *reinterpret_cast<const float4*>(W + (kk + wr) * 128 + wc4 * 4);
            *reinterpret_cast<float4*>(&Ws[wr][wc4 * 4]) = v;
        }
        // load X chunk transposed: 128 rows x 32 cols = 1024 float4
#pragma unroll
        for (int i = 0; i < 4; i++) {
            int f = t + 256 * i;
            int xr = f >> 3;
            int xc4 = f & 7;
            int gr = rowBase + xr;
            float4 v = make_float4(0.f, 0.f, 0.f, 0.f);
            if (gr < n) v = *reinterpret_cast<const float4*>(X + (size_t)gr * 128 + kk + xc4 * 4);
            Xs[xc4 * 4 + 0][xr] = v.x;
            Xs[xc4 * 4 + 1][xr] = v.y;
            Xs[xc4 * 4 + 2][xr] = v.z;
            Xs[xc4 * 4 + 3][xr] = v.w;
        }
        __syncthreads();

#pragma unroll
        for (int k = 0; k < 32; k++) {
            float4 x0 = *reinterpret_cast<const float4*>(&Xs[k][ty * 4]);
            float4 x1 = *reinterpret_cast<const float4*>(&Xs[k][64 + ty * 4]);
            float4 w0 = *reinterpret_cast<const float4*>(&Ws[k][tx * 4]);
            float4 w1 = *reinterpret_cast<const float4*>(&Ws[k][64 + tx * 4]);
            u64 wp0 = pack2f(w0.x, w0.y);
            u64 wp1 = pack2f(w0.z, w0.w);
            u64 wp2 = pack2f(w1.x, w1.y);
            u64 wp3 = pack2f(w1.z, w1.w);
            float xv[8] = {x0.x, x0.y, x0.z, x0.w, x1.x, x1.y, x1.z, x1.w};
#pragma unroll
            for (int i = 0; i < 8; i++) {
                u64 xp = pack2f(xv[i], xv[i]);
                acc2[i][0] = ffma2(xp, wp0, acc2[i][0]);
                acc2[i][1] = ffma2(xp, wp1, acc2[i][1]);
                acc2[i][2] = ffma2(xp, wp2, acc2[i][2]);
                acc2[i][3] = ffma2(xp, wp3, acc2[i][3]);
            }
        }
        __syncthreads();
    }

    // store
#pragma unroll
    for (int i = 0; i < 8; i++) {
        int rl = (i < 4) ? (ty * 4 + i) : (64 + ty * 4 + (i - 4));
        int gr = rowBase + rl;
        if (gr < n) {
            float4 v0, v1;
            unpack2f(acc2[i][0], v0.x, v0.y);
            unpack2f(acc2[i][1], v0.z, v0.w);
            unpack2f(acc2[i][2], v1.x, v1.y);
            unpack2f(acc2[i][3], v1.z, v1.w);
            *reinterpret_cast<float4*>(C + (size_t)gr * 128 + tx * 4) = v0;
            *reinterpret_cast<float4*>(C + (size_t)gr * 128 + 64 + tx * 4) = v1;
        }
    }
}

// ================= SpMM (CSR by dst, warp per row, no atomics) =================

__global__ void k_spmm(const float* __restrict__ sup, const float* __restrict__ bias,
                       float* __restrict__ out, int n, int do_relu) {
    int gt = blockIdx.x * blockDim.x + threadIdx.x;
    int row = gt >> 5;
    int lane = gt & 31;
    if (row >= n) return;

    float4 acc = *reinterpret_cast<const float4*>(bias + lane * 4);
    int e0 = g_rowptr[row];
    int e1 = g_rowptr[row + 1];

    int e = e0;
    // 2-edge unroll: 8 outstanding 16B loads per iteration for MLP
    for (; e + 2 <= e1; e += 2) {
        int s0 = __ldg(&g_csrs[e]);
        int s1 = __ldg(&g_csrs[e + 1]);
        float w0 = __ldg(&g_csrw[e]);
        float w1 = __ldg(&g_csrw[e + 1]);
        float4 v0 = *reinterpret_cast<const float4*>(sup + (size_t)s0 * 128 + lane * 4);
        float4 v1 = *reinterpret_cast<const float4*>(sup + (size_t)s1 * 128 + lane * 4);
        acc.x = fmaf(w0, v0.x, acc.x);
        acc.y = fmaf(w0, v0.y, acc.y);
        acc.z = fmaf(w0, v0.z, acc.z);
        acc.w = fmaf(w0, v0.w, acc.w);
        acc.x = fmaf(w1, v1.x, acc.x);
        acc.y = fmaf(w1, v1.y, acc.y);
        acc.z = fmaf(w1, v1.z, acc.z);
        acc.w = fmaf(w1, v1.w, acc.w);
    }
    if (e < e1) {
        int s = __ldg(&g_csrs[e]);
        float w = __ldg(&g_csrw[e]);
        float4 v = *reinterpret_cast<const float4*>(sup + (size_t)s * 128 + lane * 4);
        acc.x = fmaf(w, v.x, acc.x);
        acc.y = fmaf(w, v.y, acc.y);
        acc.z = fmaf(w, v.z, acc.z);
        acc.w = fmaf(w, v.w, acc.w);
    }

    if (do_relu) {
        acc.x = fmaxf(acc.x, 0.f);
        acc.y = fmaxf(acc.y, 0.f);
        acc.z = fmaxf(acc.z, 0.f);
        acc.w = fmaxf(acc.w, 0.f);
    }
    *reinterpret_cast<float4*>(out + (size_t)row * 128 + lane * 4) = acc;
}

// ================= launch =================

extern "C" void kernel_launch(void* const* d_in, const int* in_sizes, int n_in,
                              void* d_out, int out_size) {
    const float* features = (const float*)d_in[0];
    const int*   edge_src = (const int*)d_in[1];
    const int*   edge_dst = (const int*)d_in[2];
    const float* edge_w   = (const float*)d_in[3];
    const float* W1       = (const float*)d_in[4];
    const float* b1       = (const float*)d_in[5];
    const float* W2       = (const float*)d_in[6];
    const float* b2       = (const float*)d_in[7];
    float* out = (float*)d_out;

    int n = in_sizes[0] / DD;   // 50000
    int e = in_sizes[1];        // 1600000

    int nch = (n + 255) / 256;  // scan chunks (<=256 required)

    // device-global addresses
    float *sup, *h;
    int *degp;
    cudaGetSymbolAddress((void**)&sup, g_sup);
    cudaGetSymbolAddress((void**)&h, g_h);
    cudaGetSymbolAddress((void**)&degp, g_deg);

    // ---- CSR build (by dst) ----
    cudaMemsetAsync(degp, 0, (size_t)n * sizeof(int), 0);
    k_hist<<<(e + 511) / 512, 512>>>(edge_dst, e);
    k_scan_partial<<<nch, 256>>>(n);
    k_scan_top<<<1, 256>>>(nch);
    k_scan_final<<<nch, 256>>>(n, e);
    k_fill<<<(e + 511) / 512, 512>>>(edge_src, edge_dst, edge_w, e);

    int gemm_blocks = (n + 127) / 128;
    int spmm_blocks = (n * 32 + 255) / 256;

    // ---- layer 1 ----
    k_gemm<<<gemm_blocks, 256>>>(features, W1, sup, n);
    k_spmm<<<spmm_blocks, 256>>>(sup, b1, h, n, 1);

    // ---- layer 2 ----
    k_gemm<<<gemm_blocks, 256>>>(h, W2, sup, n);
    k_spmm<<<spmm_blocks, 256>>>(sup, b2, out, n, 0);
}

// round 6
// speedup vs baseline: 1.2321x; 1.1593x over previous
#include <cuda_runtime.h>
#include <cuda_fp16.h>

#define NMAX 50000
#define EMAX 1600000
#define DD 128

typedef unsigned long long u64;

// ---- scratch (static device globals; no allocation allowed) ----
__device__ __half g_suph[(size_t)NMAX * DD];  // support in fp16 (SpMM gather operand)
__device__ float  g_h[(size_t)NMAX * DD];     // hidden after layer 1 (fp32)
__device__ int    g_rowptr[NMAX + 1];
__device__ int    g_deg[NMAX];
__device__ int    g_fill[NMAX];
__device__ int    g_csrs[EMAX];
__device__ float  g_csrw[EMAX];
__device__ int    g_part[256];

// ---- packed f32x2 helpers (FFMA2 path; full fp32 precision) ----
__device__ __forceinline__ u64 pack2f(float a, float b) {
    u64 d;
    asm("mov.b64 %0, {%1, %2};" : "=l"(d)
        : "r"(__float_as_uint(a)), "r"(__float_as_uint(b)));
    return d;
}
__device__ __forceinline__ u64 ffma2(u64 a, u64 b, u64 c) {
    u64 d;
    asm("fma.rn.f32x2 %0, %1, %2, %3;" : "=l"(d) : "l"(a), "l"(b), "l"(c));
    return d;
}
__device__ __forceinline__ void unpack2f(u64 v, float& a, float& b) {
    unsigned int lo, hi;
    asm("mov.b64 {%0, %1}, %2;" : "=r"(lo), "=r"(hi) : "l"(v));
    a = __uint_as_float(lo);
    b = __uint_as_float(hi);
}

// ================= CSR build (scan/fill) =================

__global__ void k_scan_partial(int n) {
    __shared__ int sm[256];
    int t = threadIdx.x;
    int i = blockIdx.x * 256 + t;
    int v = (i < n) ? g_deg[i] : 0;
    sm[t] = v;
    __syncthreads();
    for (int off = 128; off > 0; off >>= 1) {
        if (t < off) sm[t] += sm[t + off];
        __syncthreads();
    }
    if (t == 0) g_part[blockIdx.x] = sm[0];
}

__global__ void k_scan_top(int nch) {
    __shared__ int sm[256];
    int t = threadIdx.x;
    int v = (t < nch) ? g_part[t] : 0;
    int x = v;
    sm[t] = x;
    __syncthreads();
    for (int off = 1; off < 256; off <<= 1) {
        int y = (t >= off) ? sm[t - off] : 0;
        __syncthreads();
        x += y;
        sm[t] = x;
        __syncthreads();
    }
    if (t < nch) g_part[t] = x - v;   // exclusive prefix of chunk sums
}

__global__ void k_scan_final(int n, int e) {
    __shared__ int sm[256];
    int t = threadIdx.x;
    int i = blockIdx.x * 256 + t;
    int v = (i < n) ? g_deg[i] : 0;
    int x = v;
    sm[t] = x;
    __syncthreads();
    for (int off = 1; off < 256; off <<= 1) {
        int y = (t >= off) ? sm[t - off] : 0;
        __syncthreads();
        x += y;
        sm[t] = x;
        __syncthreads();
    }
    int base = g_part[blockIdx.x];
    if (i < n) {
        int ex = base + x - v;
        g_rowptr[i] = ex;
        g_fill[i] = ex;
    }
    if (i == 0) g_rowptr[n] = e;
}

__global__ void k_fill(const int* __restrict__ src, const int* __restrict__ dst,
                       const float* __restrict__ w, int e) {
    int i = blockIdx.x * blockDim.x + threadIdx.x;
    if (i < e) {
        int d = dst[i];
        int p = atomicAdd(&g_fill[d], 1);
        g_csrs[p] = src[i];
        g_csrw[p] = w[i];
    }
}

// ================= GEMM (+ optional fused hist) =================
// C[n x 128] (fp16) = X[n x 128] (fp32) @ W[128 x 128] (fp32)
// 256 threads, block tile 128x128, BK=32, 8x8 per-thread tile, FFMA2 inner loop.
// Blocks >= gemmBlocks run the edge-dst histogram (grid-stride) instead.

__global__ __launch_bounds__(256, 2) void k_gemm(const float* __restrict__ X,
                                                 const float* __restrict__ W,
                                                 __half* __restrict__ C, int n,
                                                 const int* __restrict__ hist_dst,
                                                 int e, int gemmBlocks) {
    __shared__ float Ws[32][128];   // [k][col]
    __shared__ float Xs[32][132];   // [k][row], padded

    if (blockIdx.x >= gemmBlocks) {
        // ---- fused histogram (independent of GEMM) ----
        if (hist_dst) {
            int stride = (gridDim.x - gemmBlocks) * blockDim.x;
            for (int i = (blockIdx.x - gemmBlocks) * blockDim.x + threadIdx.x;
                 i < e; i += stride)
                atomicAdd(&g_deg[hist_dst[i]], 1);
        }
        return;
    }

    int t = threadIdx.x;
    int tx = t & 15;        // col group
    int ty = t >> 4;        // row group
    int rowBase = blockIdx.x * 128;

    u64 acc2[8][4];
#pragma unroll
    for (int i = 0; i < 8; i++)
#pragma unroll
        for (int j = 0; j < 4; j++) acc2[i][j] = 0ull;

    for (int kk = 0; kk < 128; kk += 32) {
#pragma unroll
        for (int i = 0; i < 4; i++) {
            int f = t + 256 * i;
            int wr = f >> 5;
            int wc4 = f & 31;
            float4 v = *reinterpret_cast<const float4*>(W + (kk + wr) * 128 + wc4 * 4);
            *reinterpret_cast<float4*>(&Ws[wr][wc4 * 4]) = v;
        }
#pragma unroll
        for (int i = 0; i < 4; i++) {
            int f = t + 256 * i;
            int xr = f >> 3;
            int xc4 = f & 7;
            int gr = rowBase + xr;
            float4 v = make_float4(0.f, 0.f, 0.f, 0.f);
            if (gr < n) v = *reinterpret_cast<const float4*>(X + (size_t)gr * 128 + kk + xc4 * 4);
            Xs[xc4 * 4 + 0][xr] = v.x;
            Xs[xc4 * 4 + 1][xr] = v.y;
            Xs[xc4 * 4 + 2][xr] = v.z;
            Xs[xc4 * 4 + 3][xr] = v.w;
        }
        __syncthreads();

#pragma unroll
        for (int k = 0; k < 32; k++) {
            float4 x0 = *reinterpret_cast<const float4*>(&Xs[k][ty * 4]);
            float4 x1 = *reinterpret_cast<const float4*>(&Xs[k][64 + ty * 4]);
            float4 w0 = *reinterpret_cast<const float4*>(&Ws[k][tx * 4]);
            float4 w1 = *reinterpret_cast<const float4*>(&Ws[k][64 + tx * 4]);
            u64 wp0 = pack2f(w0.x, w0.y);
            u64 wp1 = pack2f(w0.z, w0.w);
            u64 wp2 = pack2f(w1.x, w1.y);
            u64 wp3 = pack2f(w1.z, w1.w);
            float xv[8] = {x0.x, x0.y, x0.z, x0.w, x1.x, x1.y, x1.z, x1.w};
#pragma unroll
            for (int i = 0; i < 8; i++) {
                u64 xp = pack2f(xv[i], xv[i]);
                acc2[i][0] = ffma2(xp, wp0, acc2[i][0]);
                acc2[i][1] = ffma2(xp, wp1, acc2[i][1]);
                acc2[i][2] = ffma2(xp, wp2, acc2[i][2]);
                acc2[i][3] = ffma2(xp, wp3, acc2[i][3]);
            }
        }
        __syncthreads();
    }

    // store fp16
#pragma unroll
    for (int i = 0; i < 8; i++) {
        int rl = (i < 4) ? (ty * 4 + i) : (64 + ty * 4 + (i - 4));
        int gr = rowBase + rl;
        if (gr < n) {
            float a, b, c, d;
            uint2 p0, p1;
            unpack2f(acc2[i][0], a, b);
            unpack2f(acc2[i][1], c, d);
            __half2 h0 = __floats2half2_rn(a, b);
            __half2 h1 = __floats2half2_rn(c, d);
            p0.x = *reinterpret_cast<unsigned int*>(&h0);
            p0.y = *reinterpret_cast<unsigned int*>(&h1);
            unpack2f(acc2[i][2], a, b);
            unpack2f(acc2[i][3], c, d);
            __half2 h2 = __floats2half2_rn(a, b);
            __half2 h3 = __floats2half2_rn(c, d);
            p1.x = *reinterpret_cast<unsigned int*>(&h2);
            p1.y = *reinterpret_cast<unsigned int*>(&h3);
            *reinterpret_cast<uint2*>(C + (size_t)gr * 128 + tx * 4) = p0;
            *reinterpret_cast<uint2*>(C + (size_t)gr * 128 + 64 + tx * 4) = p1;
        }
    }
}

// ================= SpMM (CSR by dst, warp per row, fp16 gather, fp32 acc) =======

__global__ void k_spmm(const __half* __restrict__ sup, const float* __restrict__ bias,
                       float* __restrict__ out, int n, int do_relu) {
    int gt = blockIdx.x * blockDim.x + threadIdx.x;
    int row = gt >> 5;
    int lane = gt & 31;
    if (row >= n) return;

    float4 acc = *reinterpret_cast<const float4*>(bias + lane * 4);
    int e0 = g_rowptr[row];
    int e1 = g_rowptr[row + 1];

    int e = e0;
    for (; e + 4 <= e1; e += 4) {
        int s0 = __ldg(&g_csrs[e]);
        int s1 = __ldg(&g_csrs[e + 1]);
        int s2 = __ldg(&g_csrs[e + 2]);
        int s3 = __ldg(&g_csrs[e + 3]);
        float w0 = __ldg(&g_csrw[e]);
        float w1 = __ldg(&g_csrw[e + 1]);
        float w2 = __ldg(&g_csrw[e + 2]);
        float w3 = __ldg(&g_csrw[e + 3]);
        uint2 p0 = *reinterpret_cast<const uint2*>(sup + (size_t)s0 * 128 + lane * 4);
        uint2 p1 = *reinterpret_cast<const uint2*>(sup + (size_t)s1 * 128 + lane * 4);
        uint2 p2 = *reinterpret_cast<const uint2*>(sup + (size_t)s2 * 128 + lane * 4);
        uint2 p3 = *reinterpret_cast<const uint2*>(sup + (size_t)s3 * 128 + lane * 4);
        float2 a0 = __half22float2(*reinterpret_cast<__half2*>(&p0.x));
        float2 b0 = __half22float2(*reinterpret_cast<__half2*>(&p0.y));
        float2 a1 = __half22float2(*reinterpret_cast<__half2*>(&p1.x));
        float2 b1 = __half22float2(*reinterpret_cast<__half2*>(&p1.y));
        float2 a2 = __half22float2(*reinterpret_cast<__half2*>(&p2.x));
        float2 b2 = __half22float2(*reinterpret_cast<__half2*>(&p2.y));
        float2 a3 = __half22float2(*reinterpret_cast<__half2*>(&p3.x));
        float2 b3 = __half22float2(*reinterpret_cast<__half2*>(&p3.y));
        acc.x = fmaf(w0, a0.x, acc.x); acc.y = fmaf(w0, a0.y, acc.y);
        acc.z = fmaf(w0, b0.x, acc.z); acc.w = fmaf(w0, b0.y, acc.w);
        acc.x = fmaf(w1, a1.x, acc.x); acc.y = fmaf(w1, a1.y, acc.y);
        acc.z = fmaf(w1, b1.x, acc.z); acc.w = fmaf(w1, b1.y, acc.w);
        acc.x = fmaf(w2, a2.x, acc.x); acc.y = fmaf(w2, a2.y, acc.y);
        acc.z = fmaf(w2, b2.x, acc.z); acc.w = fmaf(w2, b2.y, acc.w);
        acc.x = fmaf(w3, a3.x, acc.x); acc.y = fmaf(w3, a3.y, acc.y);
        acc.z = fmaf(w3, b3.x, acc.z); acc.w = fmaf(w3, b3.y, acc.w);
    }
    for (; e < e1; e++) {
        int s = __ldg(&g_csrs[e]);
        float w = __ldg(&g_csrw[e]);
        uint2 p = *reinterpret_cast<const uint2*>(sup + (size_t)s * 128 + lane * 4);
        float2 a = __half22float2(*reinterpret_cast<__half2*>(&p.x));
        float2 b = __half22float2(*reinterpret_cast<__half2*>(&p.y));
        acc.x = fmaf(w, a.x, acc.x); acc.y = fmaf(w, a.y, acc.y);
        acc.z = fmaf(w, b.x, acc.z); acc.w = fmaf(w, b.y, acc.w);
    }

    if (do_relu) {
        acc.x = fmaxf(acc.x, 0.f);
        acc.y = fmaxf(acc.y, 0.f);
        acc.z = fmaxf(acc.z, 0.f);
        acc.w = fmaxf(acc.w, 0.f);
    }
    *reinterpret_cast<float4*>(out + (size_t)row * 128 + lane * 4) = acc;
}

// ================= launch =================

extern "C" void kernel_launch(void* const* d_in, const int* in_sizes, int n_in,
                              void* d_out, int out_size) {
    const float* features = (const float*)d_in[0];
    const int*   edge_src = (const int*)d_in[1];
    const int*   edge_dst = (const int*)d_in[2];
    const float* edge_w   = (const float*)d_in[3];
    const float* W1       = (const float*)d_in[4];
    const float* b1       = (const float*)d_in[5];
    const float* W2       = (const float*)d_in[6];
    const float* b2       = (const float*)d_in[7];
    float* out = (float*)d_out;

    int n = in_sizes[0] / DD;   // 50000
    int e = in_sizes[1];        // 1600000

    int nch = (n + 255) / 256;  // scan chunks (<=256 required)

    // device-global addresses
    __half* suph;
    float* h;
    int* degp;
    cudaGetSymbolAddress((void**)&suph, g_suph);
    cudaGetSymbolAddress((void**)&h, g_h);
    cudaGetSymbolAddress((void**)&degp, g_deg);

    int gemm_blocks = (n + 127) / 128;
    int hist_blocks = 148;
    int spmm_blocks = (n * 32 + 255) / 256;

    // ---- deg=0, then GEMM1 with fused histogram ----
    cudaMemsetAsync(degp, 0, (size_t)n * sizeof(int), 0);
    k_gemm<<<gemm_blocks + hist_blocks, 256>>>(features, W1, suph, n,
                                               edge_dst, e, gemm_blocks);

    // ---- CSR scan + fill (needs histogram done) ----
    k_scan_partial<<<nch, 256>>>(n);
    k_scan_top<<<1, 256>>>(nch);
    k_scan_final<<<nch, 256>>>(n, e);
    k_fill<<<(e + 511) / 512, 512>>>(edge_src, edge_dst, edge_w, e);

    // ---- layer 1 aggregate ----
    k_spmm<<<spmm_blocks, 256>>>(suph, b1, h, n, 1);

    // ---- layer 2 ----
    k_gemm<<<gemm_blocks, 256>>>(h, W2, suph, n, (const int*)0, 0, gemm_blocks);
    k_spmm<<<spmm_blocks, 256>>>(suph, b2, out, n, 0);
}

// round 8
// speedup vs baseline: 1.3090x; 1.0624x over previous
#include <cuda_runtime.h>
#include <cuda_fp16.h>
#include <cstdint>

#define NMAX 50000
#define EMAX 1600000
#define DD 128

// ---- scratch (static device globals; no allocation allowed) ----
__device__ __half g_suph[(size_t)NMAX * DD];  // support in fp16 (SpMM gather operand)
__device__ __half g_hh[(size_t)NMAX * DD];    // hidden after layer 1 (fp16)
__device__ __half g_w1h[DD * DD];             // W1^T in fp16 ([n][k], K-major)
__device__ __half g_w2h[DD * DD];             // W2^T in fp16
__device__ int    g_rowptr[NMAX + 1];
__device__ int    g_deg[NMAX];
__device__ int    g_fill[NMAX];
__device__ int    g_csrs[EMAX];
__device__ float  g_csrw[EMAX];
__device__ unsigned int g_state[64];          // lookback scan states

// ================= helpers =================

__device__ __forceinline__ uint32_t smem_u32(const void* p) {
    uint32_t a;
    asm("{ .reg .u64 t; cvta.to.shared.u64 t, %1; cvt.u32.u64 %0, t; }"
        : "=r"(a) : "l"(p));
    return a;
}

__device__ __forceinline__ void ldmatrix_x4(uint32_t& r0, uint32_t& r1,
                                            uint32_t& r2, uint32_t& r3, uint32_t addr) {
    asm volatile("ldmatrix.sync.aligned.m8n8.x4.shared.b16 {%0,%1,%2,%3}, [%4];"
                 : "=r"(r0), "=r"(r1), "=r"(r2), "=r"(r3) : "r"(addr));
}

__device__ __forceinline__ void mma16816(float* d, const uint32_t* a,
                                         const uint32_t* b, const float* c) {
    asm volatile(
        "mma.sync.aligned.m16n8k16.row.col.f32.f16.f16.f32 "
        "{%0,%1,%2,%3}, {%4,%5,%6,%7}, {%8,%9}, {%10,%11,%12,%13};"
        : "=f"(d[0]), "=f"(d[1]), "=f"(d[2]), "=f"(d[3])
        : "r"(a[0]), "r"(a[1]), "r"(a[2]), "r"(a[3]),
          "r"(b[0]), "r"(b[1]),
          "f"(c[0]), "f"(c[1]), "f"(c[2]), "f"(c[3]));
}

// ================= W convert/transpose (once per launch) =================

__global__ void k_wconv(const float* __restrict__ W1, const float* __restrict__ W2) {
    int i = blockIdx.x * blockDim.x + threadIdx.x;
    if (i < DD * DD) {
        int k = i >> 7, nn = i & 127;
        g_w1h[nn * DD + k] = __float2half(W1[i]);
        g_w2h[nn * DD + k] = __float2half(W2[i]);
    }
}

// ================= single-pass scan (decoupled lookback) =================
// exclusive prefix of g_deg -> g_rowptr / g_fill. tile = 2048 (256 thr x 8).

#define STILE 2048

__global__ void k_scan(int n, int e) {
    __shared__ int swarp[8];
    __shared__ int sprefix;
    int b = blockIdx.x, t = threadIdx.x, lane = t & 31, wid = t >> 5;
    int base = b * STILE + t * 8;

    int v[8];
    int s = 0;
#pragma unroll
    for (int i = 0; i < 8; i++) {
        int idx = base + i;
        v[i] = (idx < n) ? g_deg[idx] : 0;
        s += v[i];
    }
    int inc = s;
#pragma unroll
    for (int o = 1; o < 32; o <<= 1) {
        int y = __shfl_up_sync(0xffffffffu, inc, o);
        if (lane >= o) inc += y;
    }
    if (lane == 31) swarp[wid] = inc;
    __syncthreads();

    if (wid == 0) {
        int ws = (lane < 8) ? swarp[lane] : 0;
        int wi = ws;
#pragma unroll
        for (int o = 1; o < 8; o <<= 1) {
            int y = __shfl_up_sync(0xffffffffu, wi, o);
            if (lane >= o) wi += y;
        }
        int btotal = __shfl_sync(0xffffffffu, wi, 7);
        if (lane < 8) swarp[lane] = wi - ws;   // exclusive warp offsets
        if (lane == 0) {
            unsigned int agg = (unsigned int)btotal & 0x3FFFFFFFu;
            if (b == 0) {
                sprefix = 0;
                __threadfence();
                g_state[0] = agg | 0x80000000u;   // P
            } else {
                g_state[b] = agg | 0x40000000u;   // A
                __threadfence();
                unsigned int run = 0;
                int j = b - 1;
                while (true) {
                    unsigned int st = *(volatile unsigned int*)&g_state[j];
                    if (st & 0x80000000u) { run += st & 0x3FFFFFFFu; break; }
                    if (st & 0x40000000u) { run += st & 0x3FFFFFFFu; j--; }
                }
                sprefix = (int)run;
                __threadfence();
                g_state[b] = ((run + agg) & 0x3FFFFFFFu) | 0x80000000u;
            }
        }
    }
    __syncthreads();

    int run = sprefix + swarp[wid] + (inc - s);
#pragma unroll
    for (int i = 0; i < 8; i++) {
        int idx = base + i;
        if (idx < n) { g_rowptr[idx] = run; g_fill[idx] = run; }
        run += v[i];
    }
    if (b == 0 && t == 0) g_rowptr[n] = e;
}

__global__ void k_fill(const int* __restrict__ src, const int* __restrict__ dst,
                       const float* __restrict__ w, int e) {
    int i = blockIdx.x * blockDim.x + threadIdx.x;
    if (i < e) {
        int d = dst[i];
        int p = atomicAdd(&g_fill[d], 1);
        g_csrs[p] = src[i];
        g_csrw[p] = w[i];
    }
}

// ================= HMMA GEMM: C[n x 128](fp16) = X @ W (+fused hist) ============
// mma.sync m16n8k16 f32.f16.f16.f32. Per CTA: 128(M) x 128(N), K=128.
// 8 warps: warp_m = wid>>1 (32 rows each), warp_n = wid&1 (64 cols each).
// A smem: [128][136] halfs (row-major, padded); B smem: Wt [128 n][136 k] halfs.
// Blocks >= gemmBlocks run the edge-dst histogram instead.

#define AS_STRIDE 136
#define GEMM_SMEM (2 * 128 * AS_STRIDE * 2)   // 69632 B

__global__ __launch_bounds__(256)
void k_gemm_mma(const void* __restrict__ Xv, int x_is_half,
                const __half* __restrict__ Wt, __half* __restrict__ C, int n,
                const int* __restrict__ hist_dst, int e, int gemmBlocks) {
    if (blockIdx.x >= gemmBlocks) {
        if (hist_dst) {
            int stride = (gridDim.x - gemmBlocks) * blockDim.x;
            for (int i = (blockIdx.x - gemmBlocks) * blockDim.x + threadIdx.x;
                 i < e; i += stride)
                atomicAdd(&g_deg[hist_dst[i]], 1);
        }
        return;
    }

    extern __shared__ __half sm[];
    __half* As = sm;                       // [128][AS_STRIDE]
    __half* Bs = sm + 128 * AS_STRIDE;     // [128][AS_STRIDE]

    int t = threadIdx.x, wid = t >> 5, lane = t & 31;
    int wm = wid >> 1, wn = wid & 1;
    int rowBase = blockIdx.x * 128;

    // load B (Wt fp16): 128x128 halfs, 4 per thread-iter
    for (int i = t; i < 4096; i += 256) {
        int r = i >> 5, c4 = i & 31;
        uint2 v = *reinterpret_cast<const uint2*>(Wt + r * 128 + c4 * 4);
        *reinterpret_cast<uint2*>(Bs + r * AS_STRIDE + c4 * 4) = v;
    }
    // load A: X fp32 -> fp16, or fp16 passthrough
    if (x_is_half) {
        const __half* X = (const __half*)Xv;
        for (int i = t; i < 4096; i += 256) {
            int r = i >> 5, c4 = i & 31;
            int gr = rowBase + r;
            uint2 v = make_uint2(0u, 0u);
            if (gr < n) v = *reinterpret_cast<const uint2*>(X + (size_t)gr * 128 + c4 * 4);
            *reinterpret_cast<uint2*>(As + r * AS_STRIDE + c4 * 4) = v;
        }
    } else {
        const float* X = (const float*)Xv;
        for (int i = t; i < 4096; i += 256) {
            int r = i >> 5, c4 = i & 31;
            int gr = rowBase + r;
            float4 v = make_float4(0.f, 0.f, 0.f, 0.f);
            if (gr < n) v = *reinterpret_cast<const float4*>(X + (size_t)gr * 128 + c4 * 4);
            __half2 h0 = __floats2half2_rn(v.x, v.y);
            __half2 h1 = __floats2half2_rn(v.z, v.w);
            uint2 p;
            p.x = *reinterpret_cast<unsigned int*>(&h0);
            p.y = *reinterpret_cast<unsigned int*>(&h1);
            *reinterpret_cast<uint2*>(As + r * AS_STRIDE + c4 * 4) = p;
        }
    }
    __syncthreads();

    float acc[2][8][4];
#pragma unroll
    for (int mi = 0; mi < 2; mi++)
#pragma unroll
        for (int ni = 0; ni < 8; ni++)
#pragma unroll
            for (int j = 0; j < 4; j++) acc[mi][ni][j] = 0.0f;

    uint32_t asBase = smem_u32(As);
    uint32_t bsBase = smem_u32(Bs);

    // A ldmatrix address pattern: lanes0-7 rows0-7 k0 | 8-15 rows8-15 k0 |
    // 16-23 rows0-7 k8 | 24-31 rows8-15 k8
    int a_row_off = (lane & 15);
    int a_k_off = (lane >> 4) * 8;
    // B: lanes0-7 n0-7 k0 | 8-15 n0-7 k8 | 16-23 n8-15 k0 | 24-31 n8-15 k8
    int b_n_off = (lane & 7) + ((lane >> 4) & 1) * 8;
    int b_k_off = ((lane >> 3) & 1) * 8;

#pragma unroll
    for (int kk = 0; kk < 8; kk++) {
        int kc = kk * 16;
        uint32_t af[2][4];
#pragma unroll
        for (int mi = 0; mi < 2; mi++) {
            int row = wm * 32 + mi * 16 + a_row_off;
            uint32_t addr = asBase + (uint32_t)(row * AS_STRIDE + kc + a_k_off) * 2u;
            ldmatrix_x4(af[mi][0], af[mi][1], af[mi][2], af[mi][3], addr);
        }
        uint32_t bf[4][4];
#pragma unroll
        for (int bg = 0; bg < 4; bg++) {
            int nrow = wn * 64 + bg * 16 + b_n_off;
            uint32_t addr = bsBase + (uint32_t)(nrow * AS_STRIDE + kc + b_k_off) * 2u;
            ldmatrix_x4(bf[bg][0], bf[bg][1], bf[bg][2], bf[bg][3], addr);
        }
#pragma unroll
        for (int mi = 0; mi < 2; mi++)
#pragma unroll
            for (int ni = 0; ni < 8; ni++) {
                // b frag: bg = ni>>1; (r0,r1) n-tile even, (r2,r3) n-tile odd
                const uint32_t* bp = &bf[ni >> 1][(ni & 1) * 2];
                mma16816(acc[mi][ni], af[mi], bp, acc[mi][ni]);
            }
    }

    // store fp16: thread (g = lane>>2, tq = lane&3): d0,d1 -> (row g, col 2tq),
    // d2,d3 -> (row g+8, col 2tq)
    int g = lane >> 2, tq = lane & 3;
#pragma unroll
    for (int mi = 0; mi < 2; mi++) {
        int r0 = rowBase + wm * 32 + mi * 16 + g;
#pragma unroll
        for (int ni = 0; ni < 8; ni++) {
            int col = wn * 64 + ni * 8 + tq * 2;
            __half2 lo = __floats2half2_rn(acc[mi][ni][0], acc[mi][ni][1]);
            __half2 hi = __floats2half2_rn(acc[mi][ni][2], acc[mi][ni][3]);
            if (r0 < n)
                *reinterpret_cast<unsigned int*>(C + (size_t)r0 * 128 + col) =
                    *reinterpret_cast<unsigned int*>(&lo);
            if (r0 + 8 < n)
                *reinterpret_cast<unsigned int*>(C + (size_t)(r0 + 8) * 128 + col) =
                    *reinterpret_cast<unsigned int*>(&hi);
        }
    }
}

// ================= SpMM (CSR by dst, warp per row, fp16 gather, fp32 acc) =======
// outf != 0 -> fp32 output; else outh (fp16).

__global__ void k_spmm(const __half* __restrict__ sup, const float* __restrict__ bias,
                       float* __restrict__ outf, __half* __restrict__ outh,
                       int n, int do_relu) {
    int gt = blockIdx.x * blockDim.x + threadIdx.x;
    int row = gt >> 5;
    int lane = gt & 31;
    if (row >= n) return;

    float4 acc = *reinterpret_cast<const float4*>(bias + lane * 4);
    int e0 = g_rowptr[row];
    int e1 = g_rowptr[row + 1];

    int e = e0;
    for (; e + 4 <= e1; e += 4) {
        int s0 = __ldg(&g_csrs[e]);
        int s1 = __ldg(&g_csrs[e + 1]);
        int s2 = __ldg(&g_csrs[e + 2]);
        int s3 = __ldg(&g_csrs[e + 3]);
        float w0 = __ldg(&g_csrw[e]);
        float w1 = __ldg(&g_csrw[e + 1]);
        float w2 = __ldg(&g_csrw[e + 2]);
        float w3 = __ldg(&g_csrw[e + 3]);
        uint2 p0 = *reinterpret_cast<const uint2*>(sup + (size_t)s0 * 128 + lane * 4);
        uint2 p1 = *reinterpret_cast<const uint2*>(sup + (size_t)s1 * 128 + lane * 4);
        uint2 p2 = *reinterpret_cast<const uint2*>(sup + (size_t)s2 * 128 + lane * 4);
        uint2 p3 = *reinterpret_cast<const uint2*>(sup + (size_t)s3 * 128 + lane * 4);
        float2 a0 = __half22float2(*reinterpret_cast<__half2*>(&p0.x));
        float2 b0 = __half22float2(*reinterpret_cast<__half2*>(&p0.y));
        float2 a1 = __half22float2(*reinterpret_cast<__half2*>(&p1.x));
        float2 b1 = __half22float2(*reinterpret_cast<__half2*>(&p1.y));
        float2 a2 = __half22float2(*reinterpret_cast<__half2*>(&p2.x));
        float2 b2 = __half22float2(*reinterpret_cast<__half2*>(&p2.y));
        float2 a3 = __half22float2(*reinterpret_cast<__half2*>(&p3.x));
        float2 b3 = __half22float2(*reinterpret_cast<__half2*>(&p3.y));
        acc.x = fmaf(w0, a0.x, acc.x); acc.y = fmaf(w0, a0.y, acc.y);
        acc.z = fmaf(w0, b0.x, acc.z); acc.w = fmaf(w0, b0.y, acc.w);
        acc.x = fmaf(w1, a1.x, acc.x); acc.y = fmaf(w1, a1.y, acc.y);
        acc.z = fmaf(w1, b1.x, acc.z); acc.w = fmaf(w1, b1.y, acc.w);
        acc.x = fmaf(w2, a2.x, acc.x); acc.y = fmaf(w2, a2.y, acc.y);
        acc.z = fmaf(w2, b2.x, acc.z); acc.w = fmaf(w2, b2.y, acc.w);
        acc.x = fmaf(w3, a3.x, acc.x); acc.y = fmaf(w3, a3.y, acc.y);
        acc.z = fmaf(w3, b3.x, acc.z); acc.w = fmaf(w3, b3.y, acc.w);
    }
    for (; e < e1; e++) {
        int s = __ldg(&g_csrs[e]);
        float w = __ldg(&g_csrw[e]);
        uint2 p = *reinterpret_cast<const uint2*>(sup + (size_t)s * 128 + lane * 4);
        float2 a = __half22float2(*reinterpret_cast<__half2*>(&p.x));
        float2 b = __half22float2(*reinterpret_cast<__half2*>(&p.y));
        acc.x = fmaf(w, a.x, acc.x); acc.y = fmaf(w, a.y, acc.y);
        acc.z = fmaf(w, b.x, acc.z); acc.w = fmaf(w, b.y, acc.w);
    }

    if (do_relu) {
        acc.x = fmaxf(acc.x, 0.f);
        acc.y = fmaxf(acc.y, 0.f);
        acc.z = fmaxf(acc.z, 0.f);
        acc.w = fmaxf(acc.w, 0.f);
    }
    if (outf) {
        *reinterpret_cast<float4*>(outf + (size_t)row * 128 + lane * 4) = acc;
    } else {
        __half2 h0 = __floats2half2_rn(acc.x, acc.y);
        __half2 h1 = __floats2half2_rn(acc.z, acc.w);
        uint2 p;
        p.x = *reinterpret_cast<unsigned int*>(&h0);
        p.y = *reinterpret_cast<unsigned int*>(&h1);
        *reinterpret_cast<uint2*>(outh + (size_t)row * 128 + lane * 4) = p;
    }
}

// ================= launch =================

extern "C" void kernel_launch(void* const* d_in, const int* in_sizes, int n_in,
                              void* d_out, int out_size) {
    const float* features = (const float*)d_in[0];
    const int*   edge_src = (const int*)d_in[1];
    const int*   edge_dst = (const int*)d_in[2];
    const float* edge_w   = (const float*)d_in[3];
    const float* W1       = (const float*)d_in[4];
    const float* b1       = (const float*)d_in[5];
    const float* W2       = (const float*)d_in[6];
    const float* b2       = (const float*)d_in[7];
    float* out = (float*)d_out;

    int n = in_sizes[0] / DD;   // 50000
    int e = in_sizes[1];        // 1600000

    // device-global addresses
    __half *suph, *hh, *w1h, *w2h;
    int* degp;
    unsigned int* statep;
    cudaGetSymbolAddress((void**)&suph, g_suph);
    cudaGetSymbolAddress((void**)&hh, g_hh);
    cudaGetSymbolAddress((void**)&w1h, g_w1h);
    cudaGetSymbolAddress((void**)&w2h, g_w2h);
    cudaGetSymbolAddress((void**)&degp, g_deg);
    cudaGetSymbolAddress((void**)&statep, g_state);

    cudaFuncSetAttribute(k_gemm_mma, cudaFuncAttributeMaxDynamicSharedMemorySize, GEMM_SMEM);

    int gemm_blocks = (n + 127) / 128;              // 391
    int hist_blocks = 148;
    int spmm_blocks = (n * 32 + 255) / 256;
    int scan_blocks = (n + STILE - 1) / STILE;      // 25

    // ---- init + W convert ----
    cudaMemsetAsync(degp, 0, (size_t)n * sizeof(int), 0);
    cudaMemsetAsync(statep, 0, 64 * sizeof(unsigned int), 0);
    k_wconv<<<64, 256>>>(W1, W2);

    // ---- GEMM1 (HMMA) with fused edge-dst histogram ----
    k_gemm_mma<<<gemm_blocks + hist_blocks, 256, GEMM_SMEM>>>(
        features, 0, w1h, suph, n, edge_dst, e, gemm_blocks);

    // ---- CSR: single-pass scan + fill ----
    k_scan<<<scan_blocks, 256>>>(n, e);
    k_fill<<<(e + 511) / 512, 512>>>(edge_src, edge_dst, edge_w, e);

    // ---- layer 1 aggregate (fp16 out + relu) ----
    k_spmm<<<spmm_blocks, 256>>>(suph, b1, (float*)0, hh, n, 1);

    // ---- layer 2 ----
    k_gemm_mma<<<gemm_blocks, 256, GEMM_SMEM>>>(
        hh, 1, w2h, suph, n, (const int*)0, 0, gemm_blocks);
    k_spmm<<<spmm_blocks, 256>>>(suph, b2, out, (__half*)0, n, 0);
}